// round 13
// baseline (speedup 1.0000x reference)
#include <cuda_runtime.h>
#include <math.h>

#define B 8
#define S 1024
#define INDIM 512
#define H 512
#define NH 8
#define HD 64
#define BS (B*S)

// ---------------- scratch (static __device__; no allocations) ----------------
__device__ float g_h[BS*H];
__device__ float g_qkv[BS*3*H];
__device__ float g_ctx[BS*H];
__device__ float g_tmp[BS*H];
__device__ float g_hatt[BS*H];
__device__ float g_prex[BS*H];
__device__ float g_outs[BS*H];
__device__ float g_W2T[H*H];
__device__ float g_Wc[3*H*H];
__device__ float g_bc[3*H];
__device__ float g_z[B*H];
// 2 groups x 8 sub-counter lines (128B apart): arrivals spread over 8 lines
// so the 64 same-address RMWs serialize as 8x8 in parallel, not 64 in series.
__device__ __align__(128) unsigned g_sub8[512];

__global__ void init_kernel() {
    if (threadIdx.x < 512) g_sub8[threadIdx.x] = 0u;
}

// ---------------- f32x2 packed helpers ----------------
__device__ __forceinline__ void ffma2(unsigned long long &d, unsigned long long a, unsigned long long b) {
    asm("fma.rn.f32x2 %0, %1, %2, %0;" : "+l"(d) : "l"(a), "l"(b));
}
__device__ __forceinline__ unsigned long long splat2(float x) {
    unsigned long long r; asm("mov.b64 %0, {%1, %1};" : "=l"(r) : "f"(x)); return r;
}
__device__ __forceinline__ void unpack2(unsigned long long v, float &x, float &y) {
    unsigned lo, hi; asm("mov.b64 {%0, %1}, %2;" : "=r"(lo), "=r"(hi) : "l"(v));
    x = __uint_as_float(lo); y = __uint_as_float(hi);
}
__device__ __forceinline__ float hsum2(unsigned long long v) {
    float x, y; unpack2(v, x, y); return x + y;
}
__device__ __forceinline__ void ldcg2(const float* p, unsigned long long &x, unsigned long long &y) {
    asm volatile("ld.global.cg.v2.u64 {%0, %1}, [%2];" : "=l"(x), "=l"(y) : "l"(p));
}

// ---------------- small fp32 GEMM (for 512x512 Wc products) ----------------
__global__ __launch_bounds__(256) void gemm_tn(
    const float* __restrict__ A, int lda,
    const float* __restrict__ W, int ldw,
    const float* __restrict__ bias,
    float* __restrict__ C,
    int M, int N, int K)
{
    __shared__ float As[16][64];
    __shared__ float Ws[16][64];
    int tid = threadIdx.x;
    int tx = tid & 15, ty = tid >> 4;
    int bm = blockIdx.y * 64, bn = blockIdx.x * 64;
    int lr = tid >> 2;
    int lk = (tid & 3) << 2;
    const float* Ap = A + (size_t)(bm + lr) * lda + lk;
    const float* Wp = W + (size_t)(bn + lr) * ldw + lk;
    float acc[4][4];
#pragma unroll
    for (int i = 0; i < 4; i++)
#pragma unroll
        for (int j = 0; j < 4; j++) acc[i][j] = 0.f;

    for (int k0 = 0; k0 < K; k0 += 16) {
        float4 av = *(const float4*)(Ap + k0);
        float4 wv = *(const float4*)(Wp + k0);
        __syncthreads();
        As[lk + 0][lr] = av.x; As[lk + 1][lr] = av.y; As[lk + 2][lr] = av.z; As[lk + 3][lr] = av.w;
        Ws[lk + 0][lr] = wv.x; Ws[lk + 1][lr] = wv.y; Ws[lk + 2][lr] = wv.z; Ws[lk + 3][lr] = wv.w;
        __syncthreads();
#pragma unroll
        for (int kk = 0; kk < 16; kk++) {
            float4 a = *(const float4*)&As[kk][ty << 2];
            float4 w = *(const float4*)&Ws[kk][tx << 2];
            float ar[4] = {a.x, a.y, a.z, a.w};
            float wr[4] = {w.x, w.y, w.z, w.w};
#pragma unroll
            for (int i = 0; i < 4; i++)
#pragma unroll
                for (int j = 0; j < 4; j++)
                    acc[i][j] += ar[i] * wr[j];
        }
    }
#pragma unroll
    for (int j = 0; j < 4; j++) {
        int n = bn + (tx << 2) + j;
        float bv = bias ? bias[n] : 0.f;
#pragma unroll
        for (int i = 0; i < 4; i++) {
            int m = bm + (ty << 2) + i;
            C[(size_t)m * N + n] = acc[i][j] + bv;
        }
    }
}

// ---------------- big fp32 GEMM: 128x128 tile, 8x8 blocking, split subtiles ----
__global__ __launch_bounds__(256) void gemm_tn_big(
    const float* __restrict__ A, int lda,
    const float* __restrict__ W, int ldw,
    const float* __restrict__ bias,
    float* __restrict__ C,
    int M, int N, int K)
{
    __shared__ float As[16][128];
    __shared__ float Ws[16][128];
    int tid = threadIdx.x;
    int bm = blockIdx.y * 128, bn = blockIdx.x * 128;
    int lr = tid >> 1;            // 0..127: tile row
    int lk = (tid & 1) * 8;       // 0 or 8
    const float* Ap = A + (size_t)(bm + lr) * lda + lk;
    const float* Wp = W + (size_t)(bn + lr) * ldw + lk;
    int tx = tid & 15;
    int ty = tid >> 4;
    unsigned long long acc2[8][4];
#pragma unroll
    for (int i = 0; i < 8; i++)
#pragma unroll
        for (int j = 0; j < 4; j++) acc2[i][j] = 0ull;

    for (int k0 = 0; k0 < K; k0 += 16) {
        float4 a0 = *(const float4*)(Ap + k0);
        float4 a1 = *(const float4*)(Ap + k0 + 4);
        float4 w0 = *(const float4*)(Wp + k0);
        float4 w1 = *(const float4*)(Wp + k0 + 4);
        __syncthreads();
        As[lk + 0][lr] = a0.x; As[lk + 1][lr] = a0.y; As[lk + 2][lr] = a0.z; As[lk + 3][lr] = a0.w;
        As[lk + 4][lr] = a1.x; As[lk + 5][lr] = a1.y; As[lk + 6][lr] = a1.z; As[lk + 7][lr] = a1.w;
        Ws[lk + 0][lr] = w0.x; Ws[lk + 1][lr] = w0.y; Ws[lk + 2][lr] = w0.z; Ws[lk + 3][lr] = w0.w;
        Ws[lk + 4][lr] = w1.x; Ws[lk + 5][lr] = w1.y; Ws[lk + 6][lr] = w1.z; Ws[lk + 7][lr] = w1.w;
        __syncthreads();
#pragma unroll
        for (int kk = 0; kk < 16; kk++) {
            float4 alo = *(const float4*)&As[kk][ty * 4];
            float4 ahi = *(const float4*)&As[kk][64 + ty * 4];
            ulonglong2 wlo = *(const ulonglong2*)&Ws[kk][tx * 4];
            ulonglong2 whi = *(const ulonglong2*)&Ws[kk][64 + tx * 4];
            float ar[8] = {alo.x, alo.y, alo.z, alo.w, ahi.x, ahi.y, ahi.z, ahi.w};
#pragma unroll
            for (int i = 0; i < 8; i++) {
                unsigned long long aa = splat2(ar[i]);
                ffma2(acc2[i][0], aa, wlo.x);
                ffma2(acc2[i][1], aa, wlo.y);
                ffma2(acc2[i][2], aa, whi.x);
                ffma2(acc2[i][3], aa, whi.y);
            }
        }
    }
#pragma unroll
    for (int i = 0; i < 8; i++) {
        int m = bm + ((i < 4) ? (ty * 4 + i) : (64 + ty * 4 + i - 4));
#pragma unroll
        for (int g = 0; g < 2; g++) {
            int n = bn + g * 64 + tx * 4;
            float f0, f1, f2, f3;
            unpack2(acc2[i][2 * g + 0], f0, f1);
            unpack2(acc2[i][2 * g + 1], f2, f3);
            float b0 = bias ? bias[n]     : 0.f;
            float b1 = bias ? bias[n + 1] : 0.f;
            float b2v = bias ? bias[n + 2] : 0.f;
            float b3 = bias ? bias[n + 3] : 0.f;
            float4 o = make_float4(f0 + b0, f1 + b1, f2 + b2v, f3 + b3);
            *(float4*)&C[(size_t)m * N + n] = o;
        }
    }
}

// ---------------- flash attention: 2 rows/thread, quarter-dim split ----------
__global__ __launch_bounds__(128) void attn_kernel(const float* __restrict__ qkv,
                                                   float* __restrict__ ctx)
{
    __shared__ float Ks[32][64];
    __shared__ float Vs[32][64];
    int qt = blockIdx.x;          // q tile (16 x 64 rows)
    int bh = blockIdx.y;          // b*NH+h (64)
    int b = bh >> 3, h = bh & 7;
    const float* base = qkv + (size_t)b * S * 1536;
    int tid = threadIdx.x;
    int rp = tid >> 2;            // row pair 0..31
    int quarter = tid & 3;        // dim slice quarter*16..+15
    int qr = qt * 64 + rp * 2;    // rows qr, qr+1

    float4 q0[4], q1[4];
    {
        const float4* qp0 = (const float4*)(base + (size_t)qr * 1536 + h * 64 + quarter * 16);
        const float4* qp1 = (const float4*)(base + (size_t)(qr + 1) * 1536 + h * 64 + quarter * 16);
#pragma unroll
        for (int i = 0; i < 4; i++) {
            float4 t0 = qp0[i], t1 = qp1[i];
            q0[i] = make_float4(t0.x * 0.125f, t0.y * 0.125f, t0.z * 0.125f, t0.w * 0.125f);
            q1[i] = make_float4(t1.x * 0.125f, t1.y * 0.125f, t1.z * 0.125f, t1.w * 0.125f);
        }
    }
    float m0 = -1e30f, l0 = 0.f, m1 = -1e30f, l1 = 0.f;
    float4 acc0[4], acc1[4];
#pragma unroll
    for (int i = 0; i < 4; i++) {
        acc0[i] = make_float4(0.f, 0.f, 0.f, 0.f);
        acc1[i] = make_float4(0.f, 0.f, 0.f, 0.f);
    }

    for (int kt = 0; kt < 32; kt++) {
        __syncthreads();
#pragma unroll
        for (int ii = 0; ii < 4; ii++) {
            int fi = tid + 128 * ii;          // 0..511 float4s
            int row = fi >> 4;
            int d4 = (fi & 15) << 2;
            const float* kp = base + (size_t)(kt * 32 + row) * 1536 + 512 + h * 64 + d4;
            *(float4*)&Ks[row][d4] = *(const float4*)kp;
            *(float4*)&Vs[row][d4] = *(const float4*)(kp + 512);
        }
        __syncthreads();

        float s0[32], s1[32];
#pragma unroll
        for (int j = 0; j < 32; j++) {
            float a0 = 0.f, a1 = 0.f;
#pragma unroll
            for (int i = 0; i < 4; i++) {
                float4 kk = *(const float4*)&Ks[j][quarter * 16 + i * 4];
                a0 += q0[i].x * kk.x + q0[i].y * kk.y + q0[i].z * kk.z + q0[i].w * kk.w;
                a1 += q1[i].x * kk.x + q1[i].y * kk.y + q1[i].z * kk.z + q1[i].w * kk.w;
            }
            s0[j] = a0; s1[j] = a1;
        }
#pragma unroll
        for (int j = 0; j < 32; j++) {
            s0[j] += __shfl_xor_sync(0xffffffffu, s0[j], 1);
            s0[j] += __shfl_xor_sync(0xffffffffu, s0[j], 2);
            s1[j] += __shfl_xor_sync(0xffffffffu, s1[j], 1);
            s1[j] += __shfl_xor_sync(0xffffffffu, s1[j], 2);
        }

        float mx0 = s0[0], mx1 = s1[0];
#pragma unroll
        for (int j = 1; j < 32; j++) { mx0 = fmaxf(mx0, s0[j]); mx1 = fmaxf(mx1, s1[j]); }
        float mn0 = fmaxf(m0, mx0), mn1 = fmaxf(m1, mx1);
        float c0 = __expf(m0 - mn0), c1 = __expf(m1 - mn1);
        l0 *= c0; l1 *= c1;
#pragma unroll
        for (int i = 0; i < 4; i++) {
            acc0[i].x *= c0; acc0[i].y *= c0; acc0[i].z *= c0; acc0[i].w *= c0;
            acc1[i].x *= c1; acc1[i].y *= c1; acc1[i].z *= c1; acc1[i].w *= c1;
        }
        float ls0 = 0.f, ls1 = 0.f;
#pragma unroll
        for (int j = 0; j < 32; j++) {
            float p0 = __expf(s0[j] - mn0); s0[j] = p0; ls0 += p0;
            float p1 = __expf(s1[j] - mn1); s1[j] = p1; ls1 += p1;
        }
        l0 += ls0; l1 += ls1;
        m0 = mn0; m1 = mn1;

#pragma unroll
        for (int j = 0; j < 32; j++) {
            float p0 = s0[j], p1 = s1[j];
#pragma unroll
            for (int i = 0; i < 4; i++) {
                float4 vv = *(const float4*)&Vs[j][quarter * 16 + i * 4];
                acc0[i].x += p0 * vv.x; acc0[i].y += p0 * vv.y;
                acc0[i].z += p0 * vv.z; acc0[i].w += p0 * vv.w;
                acc1[i].x += p1 * vv.x; acc1[i].y += p1 * vv.y;
                acc1[i].z += p1 * vv.z; acc1[i].w += p1 * vv.w;
            }
        }
    }
    float inv0 = 1.f / l0, inv1 = 1.f / l1;
    float4* op0 = (float4*)(ctx + ((size_t)b * S + qr) * 512 + h * 64 + quarter * 16);
    float4* op1 = (float4*)(ctx + ((size_t)b * S + qr + 1) * 512 + h * 64 + quarter * 16);
#pragma unroll
    for (int i = 0; i < 4; i++) {
        op0[i] = make_float4(acc0[i].x * inv0, acc0[i].y * inv0, acc0[i].z * inv0, acc0[i].w * inv0);
        op1[i] = make_float4(acc1[i].x * inv1, acc1[i].y * inv1, acc1[i].z * inv1, acc1[i].w * inv1);
    }
}

// ---------------- fused residual + LayerNorm ----------------
__global__ __launch_bounds__(128) void ln_kernel(
    const float* __restrict__ A, const float* __restrict__ Bres,
    const float* __restrict__ gma, const float* __restrict__ bta,
    float* __restrict__ out)
{
    int row = blockIdx.x, tid = threadIdx.x;
    const float4* a4 = (const float4*)(A + (size_t)row * 512);
    const float4* b4 = (const float4*)(Bres + (size_t)row * 512);
    float4 x = a4[tid], y = b4[tid];
    float4 v = make_float4(x.x + y.x, x.y + y.y, x.z + y.z, x.w + y.w);
    float s = v.x + v.y + v.z + v.w;
    float q = v.x * v.x + v.y * v.y + v.z * v.z + v.w * v.w;
#pragma unroll
    for (int o = 16; o > 0; o >>= 1) {
        s += __shfl_down_sync(0xffffffffu, s, o);
        q += __shfl_down_sync(0xffffffffu, q, o);
    }
    __shared__ float rs[4], rq[4];
    int wid = tid >> 5;
    if ((tid & 31) == 0) { rs[wid] = s; rq[wid] = q; }
    __syncthreads();
    float ts = rs[0] + rs[1] + rs[2] + rs[3];
    float tq = rq[0] + rq[1] + rq[2] + rq[3];
    float mean = ts * (1.f / 512.f);
    float var = tq * (1.f / 512.f) - mean * mean;
    float rstd = rsqrtf(var + 1e-5f);
    float4 gg = ((const float4*)gma)[tid];
    float4 bb = ((const float4*)bta)[tid];
    float4 o;
    o.x = (v.x - mean) * rstd * gg.x + bb.x;
    o.y = (v.y - mean) * rstd * gg.y + bb.y;
    o.z = (v.z - mean) * rstd * gg.z + bb.z;
    o.w = (v.w - mean) * rstd * gg.w + bb.w;
    ((float4*)(out + (size_t)row * 512))[tid] = o;
}

// ---------------- 512x512 transpose ----------------
__global__ void transpose_kernel(const float* __restrict__ in, float* __restrict__ out)
{
    __shared__ float tile[32][33];
    int bx = blockIdx.x * 32, by = blockIdx.y * 32;
    int tx = threadIdx.x, ty = threadIdx.y;  // (32, 8)
    for (int i = 0; i < 32; i += 8)
        tile[ty + i][tx] = in[(size_t)(by + ty + i) * 512 + bx + tx];
    __syncthreads();
    for (int i = 0; i < 32; i += 8)
        out[(size_t)(bx + ty + i) * 512 + by + tx] = tile[tx][ty + i];
}

// ---------------- bc = Wfgh @ b2 + b_fgh ----------------
__global__ void bc_kernel(const float* __restrict__ tw, const float* __restrict__ gw,
                          const float* __restrict__ hw, const float* __restrict__ tb,
                          const float* __restrict__ gb, const float* __restrict__ hb,
                          const float* __restrict__ b2)
{
    int i = blockIdx.x * blockDim.x + threadIdx.x;
    if (i >= 1536) return;
    int part = i >> 9, r = i & 511;
    const float* Wr; float bv;
    if (part == 0)      { Wr = tw + (size_t)r * 512; bv = tb[r]; }
    else if (part == 1) { Wr = gw + (size_t)r * 512; bv = gb[r]; }
    else                { Wr = hw + (size_t)r * 512; bv = hb[r]; }
    float s = bv;
    for (int j = 0; j < 512; j++) s += Wr[j] * b2[j];
    g_bc[i] = s;
}

// ---------------- persistent LTC scan (R7/R10 partitioning, 8-line barrier) --
// 128 CTAs in 2 independent groups of 64 (4 batches per group).
// Barrier v3: arrivals spread over 8 sub-counter lines (8 RMWs/line serialize
// in parallel across LTS banks: ~220 cyc vs 64x27~1.7K on one line). Waiter
// polls all 8 lines with ld.relaxed.gpu (morally strong -> guaranteed
// visibility, and relaxed loads pipeline with MLP unlike acquire chains),
// then one fence.acq_rel.gpu pairs with the red.release arrivals.
#define NBLK 128
#define GRP_CTAS 64

__device__ __forceinline__ void gridbar_grp(int grp, int cblk, unsigned phase)
{
    __syncthreads();
    if (threadIdx.x == 0) {
        unsigned* base = &g_sub8[grp * 256];
        unsigned* mine = base + (cblk & 7) * 32;
        asm volatile("red.release.gpu.global.add.u32 [%0], %1;" :: "l"(mine), "r"(1u) : "memory");
        unsigned tgt = phase * 8u;
        unsigned v0, v1, v2, v3, v4, v5, v6, v7;
        do {
            asm volatile(
                "ld.relaxed.gpu.global.u32 %0, [%8];\n\t"
                "ld.relaxed.gpu.global.u32 %1, [%8+128];\n\t"
                "ld.relaxed.gpu.global.u32 %2, [%8+256];\n\t"
                "ld.relaxed.gpu.global.u32 %3, [%8+384];\n\t"
                "ld.relaxed.gpu.global.u32 %4, [%8+512];\n\t"
                "ld.relaxed.gpu.global.u32 %5, [%8+640];\n\t"
                "ld.relaxed.gpu.global.u32 %6, [%8+768];\n\t"
                "ld.relaxed.gpu.global.u32 %7, [%8+896];"
                : "=r"(v0), "=r"(v1), "=r"(v2), "=r"(v3),
                  "=r"(v4), "=r"(v5), "=r"(v6), "=r"(v7)
                : "l"(base) : "memory");
        } while (v0 < tgt || v1 < tgt || v2 < tgt || v3 < tgt ||
                 v4 < tgt || v5 < tgt || v6 < tgt || v7 < tgt);
        asm volatile("fence.acq_rel.gpu;" ::: "memory");
    }
    __syncthreads();
}

__global__ __launch_bounds__(128) void scan_kernel(const float* __restrict__ ltc_w1)
{
    __shared__ float sW1[8][512];    // W1h rows (cols) c0..c0+7
    __shared__ float sWc[24][512];   // f rows 0-7, g rows 8-15, h rows 16-23 (local)
    __shared__ float sbc[24];
    int blk = blockIdx.x, tid = threadIdx.x;
    int grp = blk >> 6;              // 0 or 1
    int cblk = blk & 63;
    int c0 = cblk * 8;
    int bbase = grp * 4;

#pragma unroll
    for (int r = 0; r < 8; r++)
        for (int k = tid; k < 512; k += 128)
            sW1[r][k] = ltc_w1[(size_t)(c0 + r) * 1024 + 512 + k];
#pragma unroll
    for (int r = 0; r < 24; r++) {
        int row = (r >> 3) * 512 + c0 + (r & 7);
        for (int k = tid; k < 512; k += 128)
            sWc[r][k] = g_Wc[(size_t)row * 512 + k];
    }
    if (tid < 24) sbc[tid] = g_bc[(tid >> 3) * 512 + c0 + (tid & 7)];
    __syncthreads();

    int w = tid >> 5, lane = tid & 31;
    int rg = w >> 1;                 // rowgroup: cols c0+4rg .. +3
    int bp = w & 1;                  // batchpair
    int b0 = bbase + 2 * bp;         // batches b0, b0+1
    int wcs = lane & 3;              // writer col-sub (lanes 0-7)
    int wb = b0 + (lane >> 2);       // writer batch (lanes 0-7)
    int wcol = c0 + 4 * rg + wcs;    // writer global column
    unsigned ph = 0;

    for (int t = 0; t < S; t++) {
        // hoisted prex load (barrier-independent)
        float prexv = 0.f;
        if (lane < 8)
            prexv = g_prex[((size_t)wb * S + t) * H + wcol];

        // ---- stage 1: z = tanh(prex + state @ W1h^T), 4 rows x 2 batches ----
        float s1 = 0.f;
        {
            unsigned long long acc[8];
#pragma unroll
            for (int r = 0; r < 8; r++) acc[r] = 0ull;
            if (t > 0) {
                const float* st0 = g_outs + ((size_t)b0 * S + (t - 1)) * H;
                const float* st1 = g_outs + ((size_t)(b0 + 1) * S + (t - 1)) * H;
#pragma unroll
                for (int i = 0; i < 4; i++) {
                    int k = lane * 4 + 128 * i;
                    unsigned long long sx0, sy0, sx1, sy1;
                    ldcg2(st0 + k, sx0, sy0);
                    ldcg2(st1 + k, sx1, sy1);
#pragma unroll
                    for (int r = 0; r < 4; r++) {
                        ulonglong2 wv = *(const ulonglong2*)&sW1[4 * rg + r][k];
                        ffma2(acc[2 * r + 0], sx0, wv.x); ffma2(acc[2 * r + 0], sy0, wv.y);
                        ffma2(acc[2 * r + 1], sx1, wv.x); ffma2(acc[2 * r + 1], sy1, wv.y);
                    }
                }
            }
#pragma unroll
            for (int r = 0; r < 8; r++) {
                float a = hsum2(acc[r]);
#pragma unroll
                for (int o = 1; o <= 16; o <<= 1)
                    a += __shfl_xor_sync(0xffffffffu, a, o);
                if (r == 2 * wcs + (lane >> 2)) s1 = a;   // writer picks its (col,batch)
            }
        }
        if (lane < 8) {
            float z = tanhf(prexv + s1);
            g_z[wb * H + wcol] = z;
        }
        gridbar_grp(grp, cblk, ++ph);

        // ---- stage 2: fgh = z @ Wc^T + bc; state update. 12 rows x 2 batches ----
        float s2[24];
        {
            unsigned long long acc[24];
#pragma unroll
            for (int r = 0; r < 24; r++) acc[r] = 0ull;
            const float* z0 = g_z + b0 * H;
            const float* z1 = g_z + (b0 + 1) * H;
#pragma unroll
            for (int i = 0; i < 4; i++) {
                int k = lane * 4 + 128 * i;
                unsigned long long zx0, zy0, zx1, zy1;
                ldcg2(z0 + k, zx0, zy0);
                ldcg2(z1 + k, zx1, zy1);
#pragma unroll
                for (int r = 0; r < 12; r++) {
                    int lrow = (r >> 2) * 8 + 4 * rg + (r & 3);
                    ulonglong2 wv = *(const ulonglong2*)&sWc[lrow][k];
                    ffma2(acc[2 * r + 0], zx0, wv.x); ffma2(acc[2 * r + 0], zy0, wv.y);
                    ffma2(acc[2 * r + 1], zx1, wv.x); ffma2(acc[2 * r + 1], zy1, wv.y);
                }
            }
#pragma unroll
            for (int r = 0; r < 24; r++) {
                float a = hsum2(acc[r]);
#pragma unroll
                for (int o = 1; o <= 16; o <<= 1)
                    a += __shfl_xor_sync(0xffffffffu, a, o);
                s2[r] = a;
            }
        }
        if (lane < 8) {
            int bsel = lane >> 2;
            float fv = s2[2 * (0 + wcs) + bsel] + sbc[0 + 4 * rg + wcs];
            float gv = s2[2 * (4 + wcs) + bsel] + sbc[8 + 4 * rg + wcs];
            float hv = s2[2 * (8 + wcs) + bsel] + sbc[16 + 4 * rg + wcs];
            float ftv = 1.f / (1.f + __expf(-fv));              // sigmoid(f)
            float gate = 1.f / (1.f + __expf(ftv * (float)t));  // sigmoid(-ft * t)
            float sv = gate * gv + (1.f - gate) * hv;
            g_outs[((size_t)wb * S + t) * H + wcol] = sv;
        }
        gridbar_grp(grp, cblk, ++ph);
    }
}

// ---------------- host launch ----------------
extern "C" void kernel_launch(void* const* d_in, const int* in_sizes, int n_in,
                              void* d_out, int out_size)
{
    const float* x    = (const float*)d_in[0];
    const float* ipw  = (const float*)d_in[1];
    const float* ipb  = (const float*)d_in[2];
    const float* qkvw = (const float*)d_in[3];
    const float* qkvb = (const float*)d_in[4];
    const float* aow  = (const float*)d_in[5];
    const float* aob  = (const float*)d_in[6];
    const float* w1   = (const float*)d_in[7];
    const float* b1   = (const float*)d_in[8];
    const float* w2   = (const float*)d_in[9];
    const float* b2   = (const float*)d_in[10];
    const float* tw   = (const float*)d_in[11];
    const float* tb   = (const float*)d_in[12];
    const float* gw   = (const float*)d_in[13];
    const float* gb   = (const float*)d_in[14];
    const float* hw   = (const float*)d_in[15];
    const float* hb   = (const float*)d_in[16];
    const float* n1g  = (const float*)d_in[17];
    const float* n1b  = (const float*)d_in[18];
    const float* n2g  = (const float*)d_in[19];
    const float* n2b  = (const float*)d_in[20];
    const float* ow   = (const float*)d_in[21];
    const float* ob   = (const float*)d_in[22];
    float* out = (float*)d_out;

    float *ph, *pqkv, *pctx, *ptmp, *phatt, *pprex, *pouts, *pW2T, *pWc;
    cudaGetSymbolAddress((void**)&ph,    g_h);
    cudaGetSymbolAddress((void**)&pqkv,  g_qkv);
    cudaGetSymbolAddress((void**)&pctx,  g_ctx);
    cudaGetSymbolAddress((void**)&ptmp,  g_tmp);
    cudaGetSymbolAddress((void**)&phatt, g_hatt);
    cudaGetSymbolAddress((void**)&pprex, g_prex);
    cudaGetSymbolAddress((void**)&pouts, g_outs);
    cudaGetSymbolAddress((void**)&pW2T,  g_W2T);
    cudaGetSymbolAddress((void**)&pWc,   g_Wc);

    init_kernel<<<1, 512>>>();

    // h = x @ in_proj_w^T + b
    gemm_tn_big<<<dim3(4, 64), 256>>>(x, 512, ipw, 512, ipb, ph, 8192, 512, 512);
    // qkv = h @ qkv_w^T + b
    gemm_tn_big<<<dim3(12, 64), 256>>>(ph, 512, qkvw, 512, qkvb, pqkv, 8192, 1536, 512);
    // attention
    attn_kernel<<<dim3(16, 64), 128>>>(pqkv, pctx);
    // attn out proj
    gemm_tn_big<<<dim3(4, 64), 256>>>(pctx, 512, aow, 512, aob, ptmp, 8192, 512, 512);
    // h_att = LN(h + attn_out)
    ln_kernel<<<8192, 128>>>(ph, ptmp, n1g, n1b, phatt);
    // prex = h_att @ W1x^T + b1  (x-half of ltc_w1, ldw = 1024)
    gemm_tn_big<<<dim3(4, 64), 256>>>(phatt, 512, w1, 1024, b1, pprex, 8192, 512, 512);
    // W2T, then Wc = [tw;gw;hw] @ W2   (as A @ (W2^T)^T)
    transpose_kernel<<<dim3(16, 16), dim3(32, 8)>>>(w2, pW2T);
    gemm_tn<<<dim3(8, 8), 256>>>(tw, 512, pW2T, 512, nullptr, pWc,            512, 512, 512);
    gemm_tn<<<dim3(8, 8), 256>>>(gw, 512, pW2T, 512, nullptr, pWc + 262144,   512, 512, 512);
    gemm_tn<<<dim3(8, 8), 256>>>(hw, 512, pW2T, 512, nullptr, pWc + 524288,   512, 512, 512);
    bc_kernel<<<6, 256>>>(tw, gw, hw, tb, gb, hb, b2);
    // persistent scan (R7 partitioning, 8-line spread barrier)
    scan_kernel<<<NBLK, 128>>>(w1);
    // LN2 + out proj
    ln_kernel<<<8192, 128>>>(pouts, phatt, n2g, n2b, ptmp);
    gemm_tn_big<<<dim3(4, 64), 256>>>(ptmp, 512, ow, 512, ob, out, 8192, 512, 512);
}

// round 15
// speedup vs baseline: 1.1064x; 1.1064x over previous
#include <cuda_runtime.h>
#include <math.h>

#define B 8
#define S 1024
#define INDIM 512
#define H 512
#define NH 8
#define HD 64
#define BS (B*S)

// ---------------- scratch (static __device__; no allocations) ----------------
__device__ float g_h[BS*H];
__device__ float g_qkv[BS*3*H];
__device__ float g_ctx[BS*H];
__device__ float g_tmp[BS*H];
__device__ float g_hatt[BS*H];
__device__ float g_prex[BS*H];
__device__ float g_outs[BS*H];
__device__ float g_W2T[H*H];
__device__ float g_Wc[3*H*H];
__device__ float g_bc[3*H];
__device__ float g_z[B*H];
__device__ __align__(128) unsigned g_barctr2[64];   // group 0 -> [0], group 1 -> [32]

__global__ void init_kernel() {
    if (threadIdx.x < 64) g_barctr2[threadIdx.x] = 0u;
}

// ---------------- f32x2 packed helpers ----------------
__device__ __forceinline__ void ffma2(unsigned long long &d, unsigned long long a, unsigned long long b) {
    asm("fma.rn.f32x2 %0, %1, %2, %0;" : "+l"(d) : "l"(a), "l"(b));
}
__device__ __forceinline__ unsigned long long splat2(float x) {
    unsigned long long r; asm("mov.b64 %0, {%1, %1};" : "=l"(r) : "f"(x)); return r;
}
__device__ __forceinline__ void unpack2(unsigned long long v, float &x, float &y) {
    unsigned lo, hi; asm("mov.b64 {%0, %1}, %2;" : "=r"(lo), "=r"(hi) : "l"(v));
    x = __uint_as_float(lo); y = __uint_as_float(hi);
}
__device__ __forceinline__ float hsum2(unsigned long long v) {
    float x, y; unpack2(v, x, y); return x + y;
}
__device__ __forceinline__ void ldcg2(const float* p, unsigned long long &x, unsigned long long &y) {
    asm volatile("ld.global.cg.v2.u64 {%0, %1}, [%2];" : "=l"(x), "=l"(y) : "l"(p));
}

// ---------------- small fp32 GEMM (for 512x512 Wc products) ----------------
__global__ __launch_bounds__(256) void gemm_tn(
    const float* __restrict__ A, int lda,
    const float* __restrict__ W, int ldw,
    const float* __restrict__ bias,
    float* __restrict__ C,
    int M, int N, int K)
{
    __shared__ float As[16][64];
    __shared__ float Ws[16][64];
    int tid = threadIdx.x;
    int tx = tid & 15, ty = tid >> 4;
    int bm = blockIdx.y * 64, bn = blockIdx.x * 64;
    int lr = tid >> 2;
    int lk = (tid & 3) << 2;
    const float* Ap = A + (size_t)(bm + lr) * lda + lk;
    const float* Wp = W + (size_t)(bn + lr) * ldw + lk;
    float acc[4][4];
#pragma unroll
    for (int i = 0; i < 4; i++)
#pragma unroll
        for (int j = 0; j < 4; j++) acc[i][j] = 0.f;

    for (int k0 = 0; k0 < K; k0 += 16) {
        float4 av = *(const float4*)(Ap + k0);
        float4 wv = *(const float4*)(Wp + k0);
        __syncthreads();
        As[lk + 0][lr] = av.x; As[lk + 1][lr] = av.y; As[lk + 2][lr] = av.z; As[lk + 3][lr] = av.w;
        Ws[lk + 0][lr] = wv.x; Ws[lk + 1][lr] = wv.y; Ws[lk + 2][lr] = wv.z; Ws[lk + 3][lr] = wv.w;
        __syncthreads();
#pragma unroll
        for (int kk = 0; kk < 16; kk++) {
            float4 a = *(const float4*)&As[kk][ty << 2];
            float4 w = *(const float4*)&Ws[kk][tx << 2];
            float ar[4] = {a.x, a.y, a.z, a.w};
            float wr[4] = {w.x, w.y, w.z, w.w};
#pragma unroll
            for (int i = 0; i < 4; i++)
#pragma unroll
                for (int j = 0; j < 4; j++)
                    acc[i][j] += ar[i] * wr[j];
        }
    }
#pragma unroll
    for (int j = 0; j < 4; j++) {
        int n = bn + (tx << 2) + j;
        float bv = bias ? bias[n] : 0.f;
#pragma unroll
        for (int i = 0; i < 4; i++) {
            int m = bm + (ty << 2) + i;
            C[(size_t)m * N + n] = acc[i][j] + bv;
        }
    }
}

// ---------------- big fp32 GEMM: 128x128 tile, 8x8 blocking, split subtiles ----
__global__ __launch_bounds__(256) void gemm_tn_big(
    const float* __restrict__ A, int lda,
    const float* __restrict__ W, int ldw,
    const float* __restrict__ bias,
    float* __restrict__ C,
    int M, int N, int K)
{
    __shared__ float As[16][128];
    __shared__ float Ws[16][128];
    int tid = threadIdx.x;
    int bm = blockIdx.y * 128, bn = blockIdx.x * 128;
    int lr = tid >> 1;            // 0..127: tile row
    int lk = (tid & 1) * 8;       // 0 or 8
    const float* Ap = A + (size_t)(bm + lr) * lda + lk;
    const float* Wp = W + (size_t)(bn + lr) * ldw + lk;
    int tx = tid & 15;
    int ty = tid >> 4;
    unsigned long long acc2[8][4];
#pragma unroll
    for (int i = 0; i < 8; i++)
#pragma unroll
        for (int j = 0; j < 4; j++) acc2[i][j] = 0ull;

    for (int k0 = 0; k0 < K; k0 += 16) {
        float4 a0 = *(const float4*)(Ap + k0);
        float4 a1 = *(const float4*)(Ap + k0 + 4);
        float4 w0 = *(const float4*)(Wp + k0);
        float4 w1 = *(const float4*)(Wp + k0 + 4);
        __syncthreads();
        As[lk + 0][lr] = a0.x; As[lk + 1][lr] = a0.y; As[lk + 2][lr] = a0.z; As[lk + 3][lr] = a0.w;
        As[lk + 4][lr] = a1.x; As[lk + 5][lr] = a1.y; As[lk + 6][lr] = a1.z; As[lk + 7][lr] = a1.w;
        Ws[lk + 0][lr] = w0.x; Ws[lk + 1][lr] = w0.y; Ws[lk + 2][lr] = w0.z; Ws[lk + 3][lr] = w0.w;
        Ws[lk + 4][lr] = w1.x; Ws[lk + 5][lr] = w1.y; Ws[lk + 6][lr] = w1.z; Ws[lk + 7][lr] = w1.w;
        __syncthreads();
#pragma unroll
        for (int kk = 0; kk < 16; kk++) {
            float4 alo = *(const float4*)&As[kk][ty * 4];
            float4 ahi = *(const float4*)&As[kk][64 + ty * 4];
            ulonglong2 wlo = *(const ulonglong2*)&Ws[kk][tx * 4];
            ulonglong2 whi = *(const ulonglong2*)&Ws[kk][64 + tx * 4];
            float ar[8] = {alo.x, alo.y, alo.z, alo.w, ahi.x, ahi.y, ahi.z, ahi.w};
#pragma unroll
            for (int i = 0; i < 8; i++) {
                unsigned long long aa = splat2(ar[i]);
                ffma2(acc2[i][0], aa, wlo.x);
                ffma2(acc2[i][1], aa, wlo.y);
                ffma2(acc2[i][2], aa, whi.x);
                ffma2(acc2[i][3], aa, whi.y);
            }
        }
    }
#pragma unroll
    for (int i = 0; i < 8; i++) {
        int m = bm + ((i < 4) ? (ty * 4 + i) : (64 + ty * 4 + i - 4));
#pragma unroll
        for (int g = 0; g < 2; g++) {
            int n = bn + g * 64 + tx * 4;
            float f0, f1, f2, f3;
            unpack2(acc2[i][2 * g + 0], f0, f1);
            unpack2(acc2[i][2 * g + 1], f2, f3);
            float b0 = bias ? bias[n]     : 0.f;
            float b1 = bias ? bias[n + 1] : 0.f;
            float b2v = bias ? bias[n + 2] : 0.f;
            float b3 = bias ? bias[n + 3] : 0.f;
            float4 o = make_float4(f0 + b0, f1 + b1, f2 + b2v, f3 + b3);
            *(float4*)&C[(size_t)m * N + n] = o;
        }
    }
}

// ---------------- flash attention: 2 rows/thread, quarter-dim split ----------
__global__ __launch_bounds__(128) void attn_kernel(const float* __restrict__ qkv,
                                                   float* __restrict__ ctx)
{
    __shared__ float Ks[32][64];
    __shared__ float Vs[32][64];
    int qt = blockIdx.x;          // q tile (16 x 64 rows)
    int bh = blockIdx.y;          // b*NH+h (64)
    int b = bh >> 3, h = bh & 7;
    const float* base = qkv + (size_t)b * S * 1536;
    int tid = threadIdx.x;
    int rp = tid >> 2;            // row pair 0..31
    int quarter = tid & 3;        // dim slice quarter*16..+15
    int qr = qt * 64 + rp * 2;    // rows qr, qr+1

    float4 q0[4], q1[4];
    {
        const float4* qp0 = (const float4*)(base + (size_t)qr * 1536 + h * 64 + quarter * 16);
        const float4* qp1 = (const float4*)(base + (size_t)(qr + 1) * 1536 + h * 64 + quarter * 16);
#pragma unroll
        for (int i = 0; i < 4; i++) {
            float4 t0 = qp0[i], t1 = qp1[i];
            q0[i] = make_float4(t0.x * 0.125f, t0.y * 0.125f, t0.z * 0.125f, t0.w * 0.125f);
            q1[i] = make_float4(t1.x * 0.125f, t1.y * 0.125f, t1.z * 0.125f, t1.w * 0.125f);
        }
    }
    float m0 = -1e30f, l0 = 0.f, m1 = -1e30f, l1 = 0.f;
    float4 acc0[4], acc1[4];
#pragma unroll
    for (int i = 0; i < 4; i++) {
        acc0[i] = make_float4(0.f, 0.f, 0.f, 0.f);
        acc1[i] = make_float4(0.f, 0.f, 0.f, 0.f);
    }

    for (int kt = 0; kt < 32; kt++) {
        __syncthreads();
#pragma unroll
        for (int ii = 0; ii < 4; ii++) {
            int fi = tid + 128 * ii;          // 0..511 float4s
            int row = fi >> 4;
            int d4 = (fi & 15) << 2;
            const float* kp = base + (size_t)(kt * 32 + row) * 1536 + 512 + h * 64 + d4;
            *(float4*)&Ks[row][d4] = *(const float4*)kp;
            *(float4*)&Vs[row][d4] = *(const float4*)(kp + 512);
        }
        __syncthreads();

        float s0[32], s1[32];
#pragma unroll
        for (int j = 0; j < 32; j++) {
            float a0 = 0.f, a1 = 0.f;
#pragma unroll
            for (int i = 0; i < 4; i++) {
                float4 kk = *(const float4*)&Ks[j][quarter * 16 + i * 4];
                a0 += q0[i].x * kk.x + q0[i].y * kk.y + q0[i].z * kk.z + q0[i].w * kk.w;
                a1 += q1[i].x * kk.x + q1[i].y * kk.y + q1[i].z * kk.z + q1[i].w * kk.w;
            }
            s0[j] = a0; s1[j] = a1;
        }
#pragma unroll
        for (int j = 0; j < 32; j++) {
            s0[j] += __shfl_xor_sync(0xffffffffu, s0[j], 1);
            s0[j] += __shfl_xor_sync(0xffffffffu, s0[j], 2);
            s1[j] += __shfl_xor_sync(0xffffffffu, s1[j], 1);
            s1[j] += __shfl_xor_sync(0xffffffffu, s1[j], 2);
        }

        float mx0 = s0[0], mx1 = s1[0];
#pragma unroll
        for (int j = 1; j < 32; j++) { mx0 = fmaxf(mx0, s0[j]); mx1 = fmaxf(mx1, s1[j]); }
        float mn0 = fmaxf(m0, mx0), mn1 = fmaxf(m1, mx1);
        float c0 = __expf(m0 - mn0), c1 = __expf(m1 - mn1);
        l0 *= c0; l1 *= c1;
#pragma unroll
        for (int i = 0; i < 4; i++) {
            acc0[i].x *= c0; acc0[i].y *= c0; acc0[i].z *= c0; acc0[i].w *= c0;
            acc1[i].x *= c1; acc1[i].y *= c1; acc1[i].z *= c1; acc1[i].w *= c1;
        }
        float ls0 = 0.f, ls1 = 0.f;
#pragma unroll
        for (int j = 0; j < 32; j++) {
            float p0 = __expf(s0[j] - mn0); s0[j] = p0; ls0 += p0;
            float p1 = __expf(s1[j] - mn1); s1[j] = p1; ls1 += p1;
        }
        l0 += ls0; l1 += ls1;
        m0 = mn0; m1 = mn1;

#pragma unroll
        for (int j = 0; j < 32; j++) {
            float p0 = s0[j], p1 = s1[j];
#pragma unroll
            for (int i = 0; i < 4; i++) {
                float4 vv = *(const float4*)&Vs[j][quarter * 16 + i * 4];
                acc0[i].x += p0 * vv.x; acc0[i].y += p0 * vv.y;
                acc0[i].z += p0 * vv.z; acc0[i].w += p0 * vv.w;
                acc1[i].x += p1 * vv.x; acc1[i].y += p1 * vv.y;
                acc1[i].z += p1 * vv.z; acc1[i].w += p1 * vv.w;
            }
        }
    }
    float inv0 = 1.f / l0, inv1 = 1.f / l1;
    float4* op0 = (float4*)(ctx + ((size_t)b * S + qr) * 512 + h * 64 + quarter * 16);
    float4* op1 = (float4*)(ctx + ((size_t)b * S + qr + 1) * 512 + h * 64 + quarter * 16);
#pragma unroll
    for (int i = 0; i < 4; i++) {
        op0[i] = make_float4(acc0[i].x * inv0, acc0[i].y * inv0, acc0[i].z * inv0, acc0[i].w * inv0);
        op1[i] = make_float4(acc1[i].x * inv1, acc1[i].y * inv1, acc1[i].z * inv1, acc1[i].w * inv1);
    }
}

// ---------------- fused residual + LayerNorm ----------------
__global__ __launch_bounds__(128) void ln_kernel(
    const float* __restrict__ A, const float* __restrict__ Bres,
    const float* __restrict__ gma, const float* __restrict__ bta,
    float* __restrict__ out)
{
    int row = blockIdx.x, tid = threadIdx.x;
    const float4* a4 = (const float4*)(A + (size_t)row * 512);
    const float4* b4 = (const float4*)(Bres + (size_t)row * 512);
    float4 x = a4[tid], y = b4[tid];
    float4 v = make_float4(x.x + y.x, x.y + y.y, x.z + y.z, x.w + y.w);
    float s = v.x + v.y + v.z + v.w;
    float q = v.x * v.x + v.y * v.y + v.z * v.z + v.w * v.w;
#pragma unroll
    for (int o = 16; o > 0; o >>= 1) {
        s += __shfl_down_sync(0xffffffffu, s, o);
        q += __shfl_down_sync(0xffffffffu, q, o);
    }
    __shared__ float rs[4], rq[4];
    int wid = tid >> 5;
    if ((tid & 31) == 0) { rs[wid] = s; rq[wid] = q; }
    __syncthreads();
    float ts = rs[0] + rs[1] + rs[2] + rs[3];
    float tq = rq[0] + rq[1] + rq[2] + rq[3];
    float mean = ts * (1.f / 512.f);
    float var = tq * (1.f / 512.f) - mean * mean;
    float rstd = rsqrtf(var + 1e-5f);
    float4 gg = ((const float4*)gma)[tid];
    float4 bb = ((const float4*)bta)[tid];
    float4 o;
    o.x = (v.x - mean) * rstd * gg.x + bb.x;
    o.y = (v.y - mean) * rstd * gg.y + bb.y;
    o.z = (v.z - mean) * rstd * gg.z + bb.z;
    o.w = (v.w - mean) * rstd * gg.w + bb.w;
    ((float4*)(out + (size_t)row * 512))[tid] = o;
}

// ---------------- 512x512 transpose ----------------
__global__ void transpose_kernel(const float* __restrict__ in, float* __restrict__ out)
{
    __shared__ float tile[32][33];
    int bx = blockIdx.x * 32, by = blockIdx.y * 32;
    int tx = threadIdx.x, ty = threadIdx.y;  // (32, 8)
    for (int i = 0; i < 32; i += 8)
        tile[ty + i][tx] = in[(size_t)(by + ty + i) * 512 + bx + tx];
    __syncthreads();
    for (int i = 0; i < 32; i += 8)
        out[(size_t)(bx + ty + i) * 512 + by + tx] = tile[tx][ty + i];
}

// ---------------- bc = Wfgh @ b2 + b_fgh ----------------
__global__ void bc_kernel(const float* __restrict__ tw, const float* __restrict__ gw,
                          const float* __restrict__ hw, const float* __restrict__ tb,
                          const float* __restrict__ gb, const float* __restrict__ hb,
                          const float* __restrict__ b2)
{
    int i = blockIdx.x * blockDim.x + threadIdx.x;
    if (i >= 1536) return;
    int part = i >> 9, r = i & 511;
    const float* Wr; float bv;
    if (part == 0)      { Wr = tw + (size_t)r * 512; bv = tb[r]; }
    else if (part == 1) { Wr = gw + (size_t)r * 512; bv = gb[r]; }
    else                { Wr = hw + (size_t)r * 512; bv = hb[r]; }
    float s = bv;
    for (int j = 0; j < 512; j++) s += Wr[j] * b2[j];
    g_bc[i] = s;
}

// ---------------- persistent LTC scan (R12 config + front-batched loads) -----
// 128 CTAs in 2 independent groups of 64 (4 batches per group). Flat per-group
// counter: red.release arrival + single acquire-load self-poll (best of 8
// measured barrier mechanisms; cost is latency/straggler-bound, not
// arrival-bound -- do not touch).
#define NBLK 128
#define GRP_CTAS 64

__device__ __forceinline__ void gridbar_grp(unsigned* ctr, unsigned target)
{
    __syncthreads();
    if (threadIdx.x == 0) {
        asm volatile("red.release.gpu.global.add.u32 [%0], %1;" :: "l"(ctr), "r"(1u) : "memory");
        unsigned v;
        do {
            asm volatile("ld.acquire.gpu.global.u32 %0, [%1];" : "=r"(v) : "l"(ctr) : "memory");
        } while (v < target);
    }
    __syncthreads();
}

__global__ __launch_bounds__(128) void scan_kernel(const float* __restrict__ ltc_w1)
{
    __shared__ float sW1[8][512];    // W1h rows (cols) c0..c0+7
    __shared__ float sWc[24][512];   // f rows 0-7, g rows 8-15, h rows 16-23 (local)
    __shared__ float sbc[24];
    int blk = blockIdx.x, tid = threadIdx.x;
    int grp = blk >> 6;              // 0 or 1
    int cblk = blk & 63;
    int c0 = cblk * 8;
    int bbase = grp * 4;
    unsigned* ctr = &g_barctr2[grp * 32];

#pragma unroll
    for (int r = 0; r < 8; r++)
        for (int k = tid; k < 512; k += 128)
            sW1[r][k] = ltc_w1[(size_t)(c0 + r) * 1024 + 512 + k];
#pragma unroll
    for (int r = 0; r < 24; r++) {
        int row = (r >> 3) * 512 + c0 + (r & 7);
        for (int k = tid; k < 512; k += 128)
            sWc[r][k] = g_Wc[(size_t)row * 512 + k];
    }
    if (tid < 24) sbc[tid] = g_bc[(tid >> 3) * 512 + c0 + (tid & 7)];
    __syncthreads();

    int w = tid >> 5, lane = tid & 31;
    int rg = w >> 1;                 // rowgroup: cols c0+4rg .. +3
    int bp = w & 1;                  // batchpair
    int b0 = bbase + 2 * bp;         // batches b0, b0+1
    int wcs = lane & 3;              // writer col-sub (lanes 0-7)
    int wb = b0 + (lane >> 2);       // writer batch (lanes 0-7)
    int wcol = c0 + 4 * rg + wcs;    // writer global column
    unsigned ph = 0;

    for (int t = 0; t < S; t++) {
        // hoisted prex load (barrier-independent)
        float prexv = 0.f;
        if (lane < 8)
            prexv = g_prex[((size_t)wb * S + t) * H + wcol];

        // ---- stage 1: z = tanh(prex + state @ W1h^T), 4 rows x 2 batches ----
        float s1 = 0.f;
        {
            unsigned long long acc[8];
#pragma unroll
            for (int r = 0; r < 8; r++) acc[r] = 0ull;
            if (t > 0) {
                const float* st0 = g_outs + ((size_t)b0 * S + (t - 1)) * H;
                const float* st1 = g_outs + ((size_t)(b0 + 1) * S + (t - 1)) * H;
                // front-batch ALL 8 L2 loads (MLP=8) before any FMA
                unsigned long long sx0[4], sy0[4], sx1[4], sy1[4];
#pragma unroll
                for (int i = 0; i < 4; i++) {
                    int k = lane * 4 + 128 * i;
                    ldcg2(st0 + k, sx0[i], sy0[i]);
                    ldcg2(st1 + k, sx1[i], sy1[i]);
                }
#pragma unroll
                for (int i = 0; i < 4; i++) {
                    int k = lane * 4 + 128 * i;
#pragma unroll
                    for (int r = 0; r < 4; r++) {
                        ulonglong2 wv = *(const ulonglong2*)&sW1[4 * rg + r][k];
                        ffma2(acc[2 * r + 0], sx0[i], wv.x); ffma2(acc[2 * r + 0], sy0[i], wv.y);
                        ffma2(acc[2 * r + 1], sx1[i], wv.x); ffma2(acc[2 * r + 1], sy1[i], wv.y);
                    }
                }
            }
#pragma unroll
            for (int r = 0; r < 8; r++) {
                float a = hsum2(acc[r]);
#pragma unroll
                for (int o = 1; o <= 16; o <<= 1)
                    a += __shfl_xor_sync(0xffffffffu, a, o);
                if (r == 2 * wcs + (lane >> 2)) s1 = a;   // writer picks its (col,batch)
            }
        }
        if (lane < 8) {
            float z = tanhf(prexv + s1);
            g_z[wb * H + wcol] = z;
        }
        gridbar_grp(ctr, (++ph) * GRP_CTAS);

        // ---- stage 2: fgh = z @ Wc^T + bc; state update. 12 rows x 2 batches ----
        float s2[24];
        {
            unsigned long long acc[24];
#pragma unroll
            for (int r = 0; r < 24; r++) acc[r] = 0ull;
            const float* z0 = g_z + b0 * H;
            const float* z1 = g_z + (b0 + 1) * H;
            // front-batch ALL 8 L2 loads (MLP=8) before any FMA
            unsigned long long zx0[4], zy0[4], zx1[4], zy1[4];
#pragma unroll
            for (int i = 0; i < 4; i++) {
                int k = lane * 4 + 128 * i;
                ldcg2(z0 + k, zx0[i], zy0[i]);
                ldcg2(z1 + k, zx1[i], zy1[i]);
            }
#pragma unroll
            for (int i = 0; i < 4; i++) {
                int k = lane * 4 + 128 * i;
#pragma unroll
                for (int r = 0; r < 12; r++) {
                    int lrow = (r >> 2) * 8 + 4 * rg + (r & 3);
                    ulonglong2 wv = *(const ulonglong2*)&sWc[lrow][k];
                    ffma2(acc[2 * r + 0], zx0[i], wv.x); ffma2(acc[2 * r + 0], zy0[i], wv.y);
                    ffma2(acc[2 * r + 1], zx1[i], wv.x); ffma2(acc[2 * r + 1], zy1[i], wv.y);
                }
            }
#pragma unroll
            for (int r = 0; r < 24; r++) {
                float a = hsum2(acc[r]);
#pragma unroll
                for (int o = 1; o <= 16; o <<= 1)
                    a += __shfl_xor_sync(0xffffffffu, a, o);
                s2[r] = a;
            }
        }
        if (lane < 8) {
            int bsel = lane >> 2;
            float fv = s2[2 * (0 + wcs) + bsel] + sbc[0 + 4 * rg + wcs];
            float gv = s2[2 * (4 + wcs) + bsel] + sbc[8 + 4 * rg + wcs];
            float hv = s2[2 * (8 + wcs) + bsel] + sbc[16 + 4 * rg + wcs];
            float ftv = 1.f / (1.f + __expf(-fv));              // sigmoid(f)
            float gate = 1.f / (1.f + __expf(ftv * (float)t));  // sigmoid(-ft * t)
            float sv = gate * gv + (1.f - gate) * hv;
            g_outs[((size_t)wb * S + t) * H + wcol] = sv;
        }
        gridbar_grp(ctr, (++ph) * GRP_CTAS);
    }
}

// ---------------- host launch ----------------
extern "C" void kernel_launch(void* const* d_in, const int* in_sizes, int n_in,
                              void* d_out, int out_size)
{
    const float* x    = (const float*)d_in[0];
    const float* ipw  = (const float*)d_in[1];
    const float* ipb  = (const float*)d_in[2];
    const float* qkvw = (const float*)d_in[3];
    const float* qkvb = (const float*)d_in[4];
    const float* aow  = (const float*)d_in[5];
    const float* aob  = (const float*)d_in[6];
    const float* w1   = (const float*)d_in[7];
    const float* b1   = (const float*)d_in[8];
    const float* w2   = (const float*)d_in[9];
    const float* b2   = (const float*)d_in[10];
    const float* tw   = (const float*)d_in[11];
    const float* tb   = (const float*)d_in[12];
    const float* gw   = (const float*)d_in[13];
    const float* gb   = (const float*)d_in[14];
    const float* hw   = (const float*)d_in[15];
    const float* hb   = (const float*)d_in[16];
    const float* n1g  = (const float*)d_in[17];
    const float* n1b  = (const float*)d_in[18];
    const float* n2g  = (const float*)d_in[19];
    const float* n2b  = (const float*)d_in[20];
    const float* ow   = (const float*)d_in[21];
    const float* ob   = (const float*)d_in[22];
    float* out = (float*)d_out;

    float *ph, *pqkv, *pctx, *ptmp, *phatt, *pprex, *pouts, *pW2T, *pWc;
    cudaGetSymbolAddress((void**)&ph,    g_h);
    cudaGetSymbolAddress((void**)&pqkv,  g_qkv);
    cudaGetSymbolAddress((void**)&pctx,  g_ctx);
    cudaGetSymbolAddress((void**)&ptmp,  g_tmp);
    cudaGetSymbolAddress((void**)&phatt, g_hatt);
    cudaGetSymbolAddress((void**)&pprex, g_prex);
    cudaGetSymbolAddress((void**)&pouts, g_outs);
    cudaGetSymbolAddress((void**)&pW2T,  g_W2T);
    cudaGetSymbolAddress((void**)&pWc,   g_Wc);

    init_kernel<<<1, 64>>>();

    // h = x @ in_proj_w^T + b
    gemm_tn_big<<<dim3(4, 64), 256>>>(x, 512, ipw, 512, ipb, ph, 8192, 512, 512);
    // qkv = h @ qkv_w^T + b
    gemm_tn_big<<<dim3(12, 64), 256>>>(ph, 512, qkvw, 512, qkvb, pqkv, 8192, 1536, 512);
    // attention
    attn_kernel<<<dim3(16, 64), 128>>>(pqkv, pctx);
    // attn out proj
    gemm_tn_big<<<dim3(4, 64), 256>>>(pctx, 512, aow, 512, aob, ptmp, 8192, 512, 512);
    // h_att = LN(h + attn_out)
    ln_kernel<<<8192, 128>>>(ph, ptmp, n1g, n1b, phatt);
    // prex = h_att @ W1x^T + b1  (x-half of ltc_w1, ldw = 1024)
    gemm_tn_big<<<dim3(4, 64), 256>>>(phatt, 512, w1, 1024, b1, pprex, 8192, 512, 512);
    // W2T, then Wc = [tw;gw;hw] @ W2   (as A @ (W2^T)^T)
    transpose_kernel<<<dim3(16, 16), dim3(32, 8)>>>(w2, pW2T);
    gemm_tn<<<dim3(8, 8), 256>>>(tw, 512, pW2T, 512, nullptr, pWc,            512, 512, 512);
    gemm_tn<<<dim3(8, 8), 256>>>(gw, 512, pW2T, 512, nullptr, pWc + 262144,   512, 512, 512);
    gemm_tn<<<dim3(8, 8), 256>>>(hw, 512, pW2T, 512, nullptr, pWc + 524288,   512, 512, 512);
    bc_kernel<<<6, 256>>>(tw, gw, hw, tb, gb, hb, b2);
    // persistent scan (R12 config + batched loads)
    scan_kernel<<<NBLK, 128>>>(w1);
    // LN2 + out proj
    ln_kernel<<<8192, 128>>>(pouts, phatt, n2g, n2b, ptmp);
    gemm_tn_big<<<dim3(4, 64), 256>>>(ptmp, 512, ow, 512, ob, out, 8192, 512, 512);
}